// round 14
// baseline (speedup 1.0000x reference)
#include <cuda_runtime.h>
#include <cuda_bf16.h>
#include <math.h>
#include <stdint.h>

// Problem constants
#define BB   8
#define CC   1024
#define CI_  512
#define DD   256
#define TT   8
#define HH   28
#define WW   28
#define NTOT 6272
#define NP   1568
#define BH   16
#define NPART 26   // 13 colblks * 2 n-warps

// Scratch (device globals: allocation-free), all GEMM operands in bf16
__device__ __nv_bfloat16 b_x [(long)BB * CC * NTOT];
__device__ __nv_bfloat16 b_xp[(long)BB * CC * NP];
__device__ __nv_bfloat16 b_w [(long)4 * CI_ * CC];     // Wg|Wph|Wth|Ww
__device__ __nv_bfloat16 b_g [(long)BB * CI_ * NP];
__device__ __nv_bfloat16 b_ph[(long)BB * CI_ * NP];
__device__ __nv_bfloat16 b_th[(long)BB * CI_ * NTOT];
__device__ __nv_bfloat16 b_y [(long)BB * CI_ * NTOT];
__device__ __nv_bfloat16 b_f [(long)BH * NTOT * NP];   // exp(logit) after f-GEMM
__device__ float         g_part[(long)BH * NTOT * NPART]; // row partial sums
__device__ float         g_inv[(long)BH * NTOT];       // 1 / rowsum

__device__ __forceinline__ uint32_t smem_u32(const void* p) {
    uint32_t a;
    asm("{ .reg .u64 t; cvta.to.shared.u64 t, %1; cvt.u32.u64 %0, t; }"
        : "=r"(a) : "l"(p));
    return a;
}
__device__ __forceinline__ void cp16(uint32_t dst, const void* src, bool p) {
    int sz = p ? 16 : 0;
    asm volatile("cp.async.cg.shared.global [%0], [%1], 16, %2;"
                 :: "r"(dst), "l"(src), "r"(sz) : "memory");
}
#define CP_COMMIT() asm volatile("cp.async.commit_group;" ::: "memory")
#define CP_WAIT0()  asm volatile("cp.async.wait_group 0;" ::: "memory")

__device__ __forceinline__ void ldsm_x4(uint32_t addr, uint32_t* r) {
    asm volatile("ldmatrix.sync.aligned.m8n8.x4.shared.b16 {%0,%1,%2,%3}, [%4];"
                 : "=r"(r[0]), "=r"(r[1]), "=r"(r[2]), "=r"(r[3]) : "r"(addr));
}
__device__ __forceinline__ void ldsm_x4_t(uint32_t addr, uint32_t* r) {
    asm volatile("ldmatrix.sync.aligned.m8n8.x4.trans.shared.b16 {%0,%1,%2,%3}, [%4];"
                 : "=r"(r[0]), "=r"(r[1]), "=r"(r[2]), "=r"(r[3]) : "r"(addr));
}

__device__ __forceinline__ uint32_t bpack(float a, float b) {
    __nv_bfloat162 t = __floats2bfloat162_rn(a, b);
    return *(uint32_t*)&t;
}

__device__ __forceinline__ void mma_bf16(float* c, const uint32_t* a, const uint32_t* b) {
    asm volatile(
        "mma.sync.aligned.m16n8k16.row.col.f32.bf16.bf16.f32 "
        "{%0,%1,%2,%3}, {%4,%5,%6,%7}, {%8,%9}, {%0,%1,%2,%3};"
        : "+f"(c[0]), "+f"(c[1]), "+f"(c[2]), "+f"(c[3])
        : "r"(a[0]), "r"(a[1]), "r"(a[2]), "r"(a[3]), "r"(b[0]), "r"(b[1]));
}

// ---------------------------------------------------------------------------
// Merged weight conversion: order Wg|Wph|Wth|Ww (g/ph stacked for fused GEMM)
// ---------------------------------------------------------------------------
__global__ void cvtw_kernel(const float4* __restrict__ w0, const float4* __restrict__ w1,
                            const float4* __restrict__ w2, const float4* __restrict__ w3,
                            __nv_bfloat162* __restrict__ out, long w4) {
    long i = (long)blockIdx.x * blockDim.x + threadIdx.x;
    if (i >= 4 * w4) return;
    int sel = (int)(i / w4);
    long j = i - (long)sel * w4;
    const float4* src = (sel == 0) ? w0 : (sel == 1) ? w1 : (sel == 2) ? w2 : w3;
    float4 v = src[j];
    out[2 * i]     = __floats2bfloat162_rn(v.x, v.y);
    out[2 * i + 1] = __floats2bfloat162_rn(v.z, v.w);
}

// ---------------------------------------------------------------------------
// Fused x conversion + MaxPool3d(1,2,2): reads x ONCE.
// Each thread handles a 4-wide x 2-tall patch (two 2x2 pooling windows):
//   reads 2 float4, writes 2 uint2 to xb (full-res bf16) and 1 u32 to xpb.
// Grid over BB*CC*TT*14*7 patches.
// ---------------------------------------------------------------------------
__global__ void cvt_pool_kernel(const float* __restrict__ x) {
    long idx = (long)blockIdx.x * blockDim.x + threadIdx.x;
    const long total = (long)BB * CC * TT * 14 * 7;
    if (idx >= total) return;
    int ow2 = idx % 7;
    int oh  = (int)((idx / 7) % 14);
    long rest = idx / 98;                     // (b*C + c)*T + t
    long base = rest * (HH * WW) + (long)oh * 2 * WW + ow2 * 4;

    float4 r0 = *(const float4*)(x + base);
    float4 r1 = *(const float4*)(x + base + WW);

    // full-res bf16
    uint2 o0 = make_uint2(bpack(r0.x, r0.y), bpack(r0.z, r0.w));
    uint2 o1 = make_uint2(bpack(r1.x, r1.y), bpack(r1.z, r1.w));
    *(uint2*)(b_x + base)      = o0;
    *(uint2*)(b_x + base + WW) = o1;

    // pooled bf16 (two windows)
    float p0 = fmaxf(fmaxf(r0.x, r0.y), fmaxf(r1.x, r1.y));
    float p1 = fmaxf(fmaxf(r0.z, r0.w), fmaxf(r1.z, r1.w));
    long pbase = rest * 196 + (long)oh * 14 + ow2 * 2;
    *(uint32_t*)(b_xp + pbase) = bpack(p0, p1);
}

// ---------------------------------------------------------------------------
// cp.async bf16 mma.sync GEMM (m16n8k16), ldmatrix, BK=32, paired-tile groups.
// BM=128, BN=128; 8 warps (4m x 2n, warp tile 32x64); 4 smem stages.
// EPI: 0=+bias->bf16; 1=exp(v*scale)->bf16 + row-partial sums into paux;
//      3=BN+residual->fp32; 4=v*colscale[n]->bf16 (colscale via bias, stride xb);
//      5=dual-half conv: rows<512 -> Cp/bias, rows>=512 -> Cp2/paux(bias2).
// ---------------------------------------------------------------------------
#define SM_BYTES 81920

template<int EPI, bool AKI, bool BKI>
__global__ void __launch_bounds__(256, 2)
tgemm_kernel(const __nv_bfloat16* __restrict__ A, long am, long ak, long ab,
             const __nv_bfloat16* __restrict__ Bp, long bk, long bn, long bb,
             void* __restrict__ Cp, long cb,
             int M, int N, int K,
             const float* __restrict__ bias, float scale,
             const float* __restrict__ gamma, const float* __restrict__ beta,
             const float* __restrict__ rmean, const float* __restrict__ rvar,
             const float* __restrict__ xres, long xb,
             void* __restrict__ Cp2, float* __restrict__ paux)
{
    extern __shared__ char smc[];
    constexpr int A_BYTES = AKI ? 128 * 80 : 32 * 272;
    constexpr int B_BYTES = BKI ? 128 * 80 : 32 * 272;
    constexpr int STG_BYTES = A_BYTES + B_BYTES;

    const int tid  = threadIdx.x;
    const int wid  = tid >> 5;
    const int lane = tid & 31;
    const int gq   = lane >> 2;
    const int qq   = lane & 3;
    const int warp_m = (wid & 3) * 32;
    const int warp_n = (wid >> 2) * 64;

    const int bz = blockIdx.z;
    const __nv_bfloat16* Ab = A  + ab * bz;
    const __nv_bfloat16* Bb = Bp + bb * bz;
    const int m0 = blockIdx.y * 128;
    const int n0 = blockIdx.x * 128;

    const uint32_t smb = smem_u32(smc);

    const int t  = lane >> 3;
    const int rr = lane & 7;
    uint32_t a_off[2], b_off;
#pragma unroll
    for (int mf = 0; mf < 2; mf++) {
        if (AKI)
            a_off[mf] = (uint32_t)((warp_m + mf * 16 + (t & 1) * 8 + rr) * 80 + (t >> 1) * 16);
        else
            a_off[mf] = (uint32_t)(((t >> 1) * 8 + rr) * 272 + (warp_m + mf * 16 + (t & 1) * 8) * 2);
    }
    if (BKI)
        b_off = (uint32_t)((warp_n + (t >> 1) * 8 + rr) * 80 + (t & 1) * 16);
    else
        b_off = (uint32_t)(((t & 1) * 8 + rr) * 272 + (warp_n + (t >> 1) * 8) * 2);

    float acc[2][8][4];
#pragma unroll
    for (int i = 0; i < 2; i++)
#pragma unroll
        for (int j = 0; j < 8; j++)
#pragma unroll
            for (int r = 0; r < 4; r++) acc[i][j][r] = 0.f;

    const int KT = K >> 5;

    auto issue = [&](int kt, int s) {
        const int k0 = kt << 5;
        uint32_t sa = smb + (uint32_t)s * STG_BYTES;
        uint32_t sb = sa + A_BYTES;
#pragma unroll
        for (int j = 0; j < 2; j++) {
            int e = tid + j * 256;
            if (AKI) {
                int m = e >> 2, ch = e & 3;
                cp16(sa + m * 80 + ch * 16,
                     Ab + (long)(m0 + m) * am + (k0 + ch * 8), true);
            } else {
                int kk = e >> 4, ch = e & 15;
                cp16(sa + kk * 272 + ch * 16,
                     Ab + (long)(k0 + kk) * ak + (m0 + ch * 8), true);
            }
        }
#pragma unroll
        for (int j = 0; j < 2; j++) {
            int e = tid + j * 256;
            if (BKI) {
                int n = e >> 2, ch = e & 3;
                bool p = (n0 + n) < N;
                int nc = p ? (n0 + n) : (N - 1);
                cp16(sb + n * 80 + ch * 16,
                     Bb + (long)nc * bn + (k0 + ch * 8), p);
            } else {
                int kk = e >> 4, ch = e & 15;
                bool p = (n0 + ch * 8) < N;
                int nc = p ? (n0 + ch * 8) : (N - 8);
                cp16(sb + kk * 272 + ch * 16,
                     Bb + (long)(k0 + kk) * bk + nc, p);
            }
        }
    };

    auto compute = [&](int s) {
        const uint32_t sa = smb + (uint32_t)s * STG_BYTES;
        const uint32_t sb = sa + A_BYTES;
#pragma unroll
        for (int ks = 0; ks < 2; ks++) {
            uint32_t afr[2][4];
#pragma unroll
            for (int mf = 0; mf < 2; mf++) {
                if (AKI) ldsm_x4  (sa + a_off[mf] + ks * 32,   afr[mf]);
                else     ldsm_x4_t(sa + a_off[mf] + ks * 4352, afr[mf]);
            }
#pragma unroll
            for (int nf2 = 0; nf2 < 4; nf2++) {
                uint32_t bfr[4];
                if (BKI) ldsm_x4  (sb + b_off + nf2 * 1280 + ks * 32,   bfr);
                else     ldsm_x4_t(sb + b_off + nf2 * 32   + ks * 4352, bfr);
                mma_bf16(acc[0][2 * nf2],     afr[0], bfr);
                mma_bf16(acc[1][2 * nf2],     afr[1], bfr);
                mma_bf16(acc[0][2 * nf2 + 1], afr[0], bfr + 2);
                mma_bf16(acc[1][2 * nf2 + 1], afr[1], bfr + 2);
            }
        }
    };

    // prologue: first pair (group 0)
    issue(0, 0);
    if (KT > 1) issue(1, 1);
    CP_COMMIT();

    int kt = 0;
    for (; kt + 1 < KT; kt += 2) {
        CP_WAIT0();
        __syncthreads();
        if (kt + 2 < KT) {
            issue(kt + 2, (kt + 2) & 3);
            if (kt + 3 < KT) issue(kt + 3, (kt + 3) & 3);
            CP_COMMIT();
        }
        compute(kt & 3);
        compute((kt + 1) & 3);
    }
    if (kt < KT) {                  // odd-KT tail
        CP_WAIT0();
        __syncthreads();
        compute(kt & 3);
    }

    // epilogue
    if (EPI == 3) {
        float* Cb = (float*)Cp + cb * bz;
#pragma unroll
        for (int mf = 0; mf < 2; mf++) {
            int r1 = m0 + warp_m + mf * 16 + gq;
            int r2 = r1 + 8;
            float b1 = bias[r1], b2 = bias[r2];
            float i1 = gamma[r1] * rsqrtf(rvar[r1] + 1e-5f);
            float i2 = gamma[r2] * rsqrtf(rvar[r2] + 1e-5f);
            float s1 = beta[r1] - rmean[r1] * i1;
            float s2 = beta[r2] - rmean[r2] * i2;
#pragma unroll
            for (int nf = 0; nf < 8; nf++) {
                int col = n0 + warp_n + nf * 8 + 2 * qq;
                if (col >= N) continue;
                const float* xr = xres + xb * bz;
                float2 x1 = *(const float2*)(xr + (long)r1 * N + col);
                float2 x2 = *(const float2*)(xr + (long)r2 * N + col);
                float v0 = (acc[mf][nf][0] + b1) * i1 + s1 + x1.x;
                float v1 = (acc[mf][nf][1] + b1) * i1 + s1 + x1.y;
                float v2 = (acc[mf][nf][2] + b2) * i2 + s2 + x2.x;
                float v3 = (acc[mf][nf][3] + b2) * i2 + s2 + x2.y;
                *(float2*)(Cb + (long)r1 * N + col) = make_float2(v0, v1);
                *(float2*)(Cb + (long)r2 * N + col) = make_float2(v2, v3);
            }
        }
    } else {
        const int half = (EPI == 5 && m0 >= 512) ? 1 : 0;
        __nv_bfloat16* Cb = ((__nv_bfloat16*)(half ? Cp2 : Cp)) + cb * bz;
        const int rbase = half ? 512 : 0;
#pragma unroll
        for (int mf = 0; mf < 2; mf++) {
            int r1 = m0 + warp_m + mf * 16 + gq;
            int r2 = r1 + 8;
            float b1 = 0.f, b2 = 0.f;
            if (EPI == 0) { b1 = bias[r1]; b2 = bias[r2]; }
            if (EPI == 5) {
                const float* bp = half ? paux : bias;
                b1 = bp[r1 - rbase]; b2 = bp[r2 - rbase];
            }
            float s1 = 0.f, s2 = 0.f;   // EPI==1 row partial sums
#pragma unroll
            for (int nf = 0; nf < 8; nf++) {
                int col = n0 + warp_n + nf * 8 + 2 * qq;
                if (col >= N) continue;
                float v0 = acc[mf][nf][0], v1 = acc[mf][nf][1];
                float v2 = acc[mf][nf][2], v3 = acc[mf][nf][3];
                if (EPI == 0 || EPI == 5) { v0 += b1; v1 += b1; v2 += b2; v3 += b2; }
                if (EPI == 1) {
                    v0 = __expf(v0 * scale); v1 = __expf(v1 * scale);
                    v2 = __expf(v2 * scale); v3 = __expf(v3 * scale);
                    s1 += v0 + v1; s2 += v2 + v3;
                }
                if (EPI == 4) {
                    float2 iv = *(const float2*)(bias + xb * bz + col);
                    v0 *= iv.x; v1 *= iv.y; v2 *= iv.x; v3 *= iv.y;
                }
                *(uint32_t*)(Cb + (long)(r1 - rbase) * N + col) = bpack(v0, v1);
                *(uint32_t*)(Cb + (long)(r2 - rbase) * N + col) = bpack(v2, v3);
            }
            if (EPI == 1) {
                s1 += __shfl_xor_sync(0xFFFFFFFFu, s1, 1);
                s1 += __shfl_xor_sync(0xFFFFFFFFu, s1, 2);
                s2 += __shfl_xor_sync(0xFFFFFFFFu, s2, 1);
                s2 += __shfl_xor_sync(0xFFFFFFFFu, s2, 2);
                if (qq == 0) {
                    int pidx = blockIdx.x * 2 + (wid >> 2);
                    paux[((long)bz * NTOT + r1) * NPART + pidx] = s1;
                    paux[((long)bz * NTOT + r2) * NPART + pidx] = s2;
                }
            }
        }
    }
}

// ---------------------------------------------------------------------------
// Reduce 26 partials per row -> 1/sum (fixed order, deterministic).
// ---------------------------------------------------------------------------
__global__ void reduce_inv_kernel(const float* __restrict__ part,
                                  float* __restrict__ inv) {
    long r = (long)blockIdx.x * blockDim.x + threadIdx.x;
    if (r >= (long)BH * NTOT) return;
    const float* p = part + r * NPART;
    float s = 0.f;
#pragma unroll
    for (int i = 0; i < NPART; i++) s += p[i];
    inv[r] = 1.f / s;
}

// ---------------------------------------------------------------------------
extern "C" void kernel_launch(void* const* d_in, const int* in_sizes, int n_in,
                              void* d_out, int out_size)
{
    const float* x     = (const float*)d_in[0];
    const float* Wg    = (const float*)d_in[1];
    const float* bg    = (const float*)d_in[2];
    const float* Wth   = (const float*)d_in[3];
    const float* bth   = (const float*)d_in[4];
    const float* Wph   = (const float*)d_in[5];
    const float* bph   = (const float*)d_in[6];
    const float* Ww    = (const float*)d_in[7];
    const float* bw    = (const float*)d_in[8];
    const float* gamma = (const float*)d_in[9];
    const float* beta  = (const float*)d_in[10];
    const float* rmean = (const float*)d_in[11];
    const float* rvar  = (const float*)d_in[12];
    float* out = (float*)d_out;

    __nv_bfloat16 *xb, *xpb, *wb, *gb, *phb, *thb, *yb, *fb;
    float *invb, *partb;
    cudaGetSymbolAddress((void**)&xb,    b_x);
    cudaGetSymbolAddress((void**)&xpb,   b_xp);
    cudaGetSymbolAddress((void**)&wb,    b_w);
    cudaGetSymbolAddress((void**)&gb,    b_g);
    cudaGetSymbolAddress((void**)&phb,   b_ph);
    cudaGetSymbolAddress((void**)&thb,   b_th);
    cudaGetSymbolAddress((void**)&yb,    b_y);
    cudaGetSymbolAddress((void**)&fb,    b_f);
    cudaGetSymbolAddress((void**)&invb,  g_inv);
    cudaGetSymbolAddress((void**)&partb, g_part);

    cudaFuncSetAttribute(tgemm_kernel<5, true,  false>, cudaFuncAttributeMaxDynamicSharedMemorySize, SM_BYTES);
    cudaFuncSetAttribute(tgemm_kernel<0, true,  false>, cudaFuncAttributeMaxDynamicSharedMemorySize, SM_BYTES);
    cudaFuncSetAttribute(tgemm_kernel<1, false, false>, cudaFuncAttributeMaxDynamicSharedMemorySize, SM_BYTES);
    cudaFuncSetAttribute(tgemm_kernel<4, true,  true >, cudaFuncAttributeMaxDynamicSharedMemorySize, SM_BYTES);
    cudaFuncSetAttribute(tgemm_kernel<3, true,  false>, cudaFuncAttributeMaxDynamicSharedMemorySize, SM_BYTES);

    const long WSZ = (long)CI_ * CC;   // 524288

    // 0) weights -> bf16 (order Wg|Wph|Wth|Ww)
    {
        long w4 = WSZ / 4;
        cvtw_kernel<<<(unsigned)((4 * w4 + 255) / 256), 256>>>(
            (const float4*)Wg, (const float4*)Wph, (const float4*)Wth, (const float4*)Ww,
            (__nv_bfloat162*)wb, w4);
    }
    // 1) fused x -> bf16 + maxpool -> bf16 (reads x once)
    {
        long total = (long)BB * CC * TT * 14 * 7;
        cvt_pool_kernel<<<(unsigned)((total + 255) / 256), 256>>>(x);
    }

    // 2) fused [g; ph] = [Wg; Wph] @ xp + [bg; bph]  (M=1024, N=1568, K=1024, batch 8)
    {
        dim3 grid((NP + 127) / 128, 1024 / 128, BB);
        tgemm_kernel<5, true, false><<<grid, 256, SM_BYTES>>>(
            wb, CC, 1, 0,
            xpb, NP, 1, (long)CC * NP,
            gb, (long)CI_ * NP,
            1024, NP, CC,
            bg, 0.f, nullptr, nullptr, nullptr, nullptr, nullptr, 0,
            phb, (float*)bph);
    }
    // 3) th = Wth @ x + bth   (M=512, N=6272, K=1024, batch 8)
    {
        dim3 grid(NTOT / 128, CI_ / 128, BB);
        tgemm_kernel<0, true, false><<<grid, 256, SM_BYTES>>>(
            wb + 2 * WSZ, CC, 1, 0,
            xb, NTOT, 1, (long)CC * NTOT,
            thb, (long)CI_ * NTOT,
            CI_, NTOT, CC,
            bth, 0.f, nullptr, nullptr, nullptr, nullptr, nullptr, 0,
            nullptr, nullptr);
    }
    // 4) f = exp(th^T @ ph * d^-0.5) + row partial sums  (M=6272, N=1568, K=256, batch 16)
    {
        dim3 grid((NP + 127) / 128, NTOT / 128, BH);
        tgemm_kernel<1, false, false><<<grid, 256, SM_BYTES>>>(
            thb, 1, NTOT, (long)DD * NTOT,
            phb, NP, 1, (long)DD * NP,
            fb, (long)NTOT * NP,
            NTOT, NP, DD,
            nullptr, 0.0625f, nullptr, nullptr, nullptr, nullptr, nullptr, 0,
            nullptr, partb);
    }
    // 5) reduce partials -> 1/sum
    reduce_inv_kernel<<<(BH * NTOT + 255) / 256, 256>>>(partb, invb);

    // 6) y = (g @ f^T) * colinv   (M=256, N=6272, K=1568, batch 16)
    {
        dim3 grid(NTOT / 128, DD / 128, BH);
        tgemm_kernel<4, true, true><<<grid, 256, SM_BYTES>>>(
            gb, NP, 1, (long)DD * NP,
            fb, 1, NP, (long)NTOT * NP,
            yb, (long)DD * NTOT,
            DD, NTOT, NP,
            invb, 0.f, nullptr, nullptr, nullptr, nullptr, nullptr, NTOT,
            nullptr, nullptr);
    }
    // 7) out = BN(Ww @ y + bw) + x   (M=1024, N=6272, K=512, batch 8)
    {
        dim3 grid(NTOT / 128, CC / 128, BB);
        tgemm_kernel<3, true, false><<<grid, 256, SM_BYTES>>>(
            wb + 3 * WSZ, CI_, 1, 0,
            yb, NTOT, 1, (long)CI_ * NTOT,
            out, (long)CC * NTOT,
            CC, NTOT, CI_,
            bw, 0.f, gamma, beta, rmean, rvar, x, (long)CC * NTOT,
            nullptr, nullptr);
    }
}

// round 15
// speedup vs baseline: 1.4563x; 1.4563x over previous
#include <cuda_runtime.h>
#include <cuda_bf16.h>
#include <math.h>
#include <stdint.h>

// Problem constants
#define BB   8
#define CC   1024
#define CI_  512
#define DD   256
#define TT   8
#define HH   28
#define WW   28
#define NTOT 6272
#define NP   1568
#define BH   16
#define NPART 26   // 13 colblks * 2 n-warps

// Scratch (device globals: allocation-free), all GEMM operands in bf16
__device__ __nv_bfloat16 b_x [(long)BB * CC * NTOT];
__device__ __nv_bfloat16 b_xp[(long)BB * CC * NP];
__device__ __nv_bfloat16 b_w [(long)4 * CI_ * CC];     // Wg|Wph|Wth|Ww
__device__ __nv_bfloat16 b_g [(long)BB * CI_ * NP];
__device__ __nv_bfloat16 b_ph[(long)BB * CI_ * NP];
__device__ __nv_bfloat16 b_th[(long)BB * CI_ * NTOT];
__device__ __nv_bfloat16 b_y [(long)BB * CI_ * NTOT];
__device__ __nv_bfloat16 b_f [(long)BH * NTOT * NP];   // exp(logit) after f-GEMM
__device__ float         g_part[(long)BH * NTOT * NPART]; // row partial sums
__device__ float         g_inv[(long)BH * NTOT];       // 1 / rowsum

__device__ __forceinline__ uint32_t smem_u32(const void* p) {
    uint32_t a;
    asm("{ .reg .u64 t; cvta.to.shared.u64 t, %1; cvt.u32.u64 %0, t; }"
        : "=r"(a) : "l"(p));
    return a;
}
__device__ __forceinline__ void cp16(uint32_t dst, const void* src, bool p) {
    int sz = p ? 16 : 0;
    asm volatile("cp.async.cg.shared.global [%0], [%1], 16, %2;"
                 :: "r"(dst), "l"(src), "r"(sz) : "memory");
}
#define CP_COMMIT() asm volatile("cp.async.commit_group;" ::: "memory")
#define CP_WAIT0()  asm volatile("cp.async.wait_group 0;" ::: "memory")

__device__ __forceinline__ void ldsm_x4(uint32_t addr, uint32_t* r) {
    asm volatile("ldmatrix.sync.aligned.m8n8.x4.shared.b16 {%0,%1,%2,%3}, [%4];"
                 : "=r"(r[0]), "=r"(r[1]), "=r"(r[2]), "=r"(r[3]) : "r"(addr));
}
__device__ __forceinline__ void ldsm_x4_t(uint32_t addr, uint32_t* r) {
    asm volatile("ldmatrix.sync.aligned.m8n8.x4.trans.shared.b16 {%0,%1,%2,%3}, [%4];"
                 : "=r"(r[0]), "=r"(r[1]), "=r"(r[2]), "=r"(r[3]) : "r"(addr));
}

__device__ __forceinline__ uint32_t bpack(float a, float b) {
    __nv_bfloat162 t = __floats2bfloat162_rn(a, b);
    return *(uint32_t*)&t;
}

__device__ __forceinline__ void mma_bf16(float* c, const uint32_t* a, const uint32_t* b) {
    asm volatile(
        "mma.sync.aligned.m16n8k16.row.col.f32.bf16.bf16.f32 "
        "{%0,%1,%2,%3}, {%4,%5,%6,%7}, {%8,%9}, {%0,%1,%2,%3};"
        : "+f"(c[0]), "+f"(c[1]), "+f"(c[2]), "+f"(c[3])
        : "r"(a[0]), "r"(a[1]), "r"(a[2]), "r"(a[3]), "r"(b[0]), "r"(b[1]));
}

// ---------------------------------------------------------------------------
// Combined fp32->bf16 conversion: x (n4 float4) then Wg|Wph|Wth|Ww (w4 each).
// Same per-element ops as the previous separate cvtb/cvtw kernels.
// ---------------------------------------------------------------------------
__global__ void cvt_all_kernel(const float4* __restrict__ xin,
                               __nv_bfloat162* __restrict__ xout, long n4,
                               const float4* __restrict__ w0, const float4* __restrict__ w1,
                               const float4* __restrict__ w2, const float4* __restrict__ w3,
                               __nv_bfloat162* __restrict__ wout, long w4) {
    long i = (long)blockIdx.x * blockDim.x + threadIdx.x;
    if (i < n4) {
        float4 v = xin[i];
        xout[2 * i]     = __floats2bfloat162_rn(v.x, v.y);
        xout[2 * i + 1] = __floats2bfloat162_rn(v.z, v.w);
        return;
    }
    long j = i - n4;
    if (j >= 4 * w4) return;
    int sel = (int)(j / w4);
    long jj = j - (long)sel * w4;
    const float4* src = (sel == 0) ? w0 : (sel == 1) ? w1 : (sel == 2) ? w2 : w3;
    float4 v = src[jj];
    wout[2 * j]     = __floats2bfloat162_rn(v.x, v.y);
    wout[2 * j + 1] = __floats2bfloat162_rn(v.z, v.w);
}

// ---------------------------------------------------------------------------
// MaxPool3d(1,2,2) over the bf16 xb (monotone rounding => identical to
// pooling fp32 then rounding). Reads 103MB instead of 205MB.
// ---------------------------------------------------------------------------
__global__ void maxpool_kernel() {
    long idx = (long)blockIdx.x * blockDim.x + threadIdx.x;
    const long total = (long)BB * CC * TT * 14 * 14;
    if (idx >= total) return;
    int ow = idx % 14;
    int oh = (idx / 14) % 14;
    long rest = idx / 196;
    long base = rest * (HH * WW) + (long)(oh * 2) * WW + ow * 2;
    float a0 = __bfloat162float(b_x[base]);
    float a1 = __bfloat162float(b_x[base + 1]);
    float a2 = __bfloat162float(b_x[base + WW]);
    float a3 = __bfloat162float(b_x[base + WW + 1]);
    float m = fmaxf(fmaxf(a0, a1), fmaxf(a2, a3));
    b_xp[idx] = __float2bfloat16_rn(m);   // values are already bf16-exact
}

// ---------------------------------------------------------------------------
// cp.async bf16 mma.sync GEMM (m16n8k16), ldmatrix, BK=32, paired-tile groups.
// BM=128, BN=128; 8 warps (4m x 2n, warp tile 32x64); 4 smem stages.
// EPI: 0=+bias->bf16; 1=exp(v*scale)->bf16 + row-partial sums into paux;
//      3=BN+residual->fp32; 4=v*colscale[n]->bf16 (colscale via bias, stride xb);
//      5=dual-half conv: rows<512 -> Cp/bias, rows>=512 -> Cp2/paux(bias2).
// ---------------------------------------------------------------------------
#define SM_BYTES 81920

template<int EPI, bool AKI, bool BKI>
__global__ void __launch_bounds__(256, 2)
tgemm_kernel(const __nv_bfloat16* __restrict__ A, long am, long ak, long ab,
             const __nv_bfloat16* __restrict__ Bp, long bk, long bn, long bb,
             void* __restrict__ Cp, long cb,
             int M, int N, int K,
             const float* __restrict__ bias, float scale,
             const float* __restrict__ gamma, const float* __restrict__ beta,
             const float* __restrict__ rmean, const float* __restrict__ rvar,
             const float* __restrict__ xres, long xb,
             void* __restrict__ Cp2, float* __restrict__ paux)
{
    extern __shared__ char smc[];
    constexpr int A_BYTES = AKI ? 128 * 80 : 32 * 272;
    constexpr int B_BYTES = BKI ? 128 * 80 : 32 * 272;
    constexpr int STG_BYTES = A_BYTES + B_BYTES;

    const int tid  = threadIdx.x;
    const int wid  = tid >> 5;
    const int lane = tid & 31;
    const int gq   = lane >> 2;
    const int qq   = lane & 3;
    const int warp_m = (wid & 3) * 32;
    const int warp_n = (wid >> 2) * 64;

    const int bz = blockIdx.z;
    const __nv_bfloat16* Ab = A  + ab * bz;
    const __nv_bfloat16* Bb = Bp + bb * bz;
    const int m0 = blockIdx.y * 128;
    const int n0 = blockIdx.x * 128;

    const uint32_t smb = smem_u32(smc);

    const int t  = lane >> 3;
    const int rr = lane & 7;
    uint32_t a_off[2], b_off;
#pragma unroll
    for (int mf = 0; mf < 2; mf++) {
        if (AKI)
            a_off[mf] = (uint32_t)((warp_m + mf * 16 + (t & 1) * 8 + rr) * 80 + (t >> 1) * 16);
        else
            a_off[mf] = (uint32_t)(((t >> 1) * 8 + rr) * 272 + (warp_m + mf * 16 + (t & 1) * 8) * 2);
    }
    if (BKI)
        b_off = (uint32_t)((warp_n + (t >> 1) * 8 + rr) * 80 + (t & 1) * 16);
    else
        b_off = (uint32_t)(((t & 1) * 8 + rr) * 272 + (warp_n + (t >> 1) * 8) * 2);

    float acc[2][8][4];
#pragma unroll
    for (int i = 0; i < 2; i++)
#pragma unroll
        for (int j = 0; j < 8; j++)
#pragma unroll
            for (int r = 0; r < 4; r++) acc[i][j][r] = 0.f;

    const int KT = K >> 5;

    auto issue = [&](int kt, int s) {
        const int k0 = kt << 5;
        uint32_t sa = smb + (uint32_t)s * STG_BYTES;
        uint32_t sb = sa + A_BYTES;
#pragma unroll
        for (int j = 0; j < 2; j++) {
            int e = tid + j * 256;
            if (AKI) {
                int m = e >> 2, ch = e & 3;
                cp16(sa + m * 80 + ch * 16,
                     Ab + (long)(m0 + m) * am + (k0 + ch * 8), true);
            } else {
                int kk = e >> 4, ch = e & 15;
                cp16(sa + kk * 272 + ch * 16,
                     Ab + (long)(k0 + kk) * ak + (m0 + ch * 8), true);
            }
        }
#pragma unroll
        for (int j = 0; j < 2; j++) {
            int e = tid + j * 256;
            if (BKI) {
                int n = e >> 2, ch = e & 3;
                bool p = (n0 + n) < N;
                int nc = p ? (n0 + n) : (N - 1);
                cp16(sb + n * 80 + ch * 16,
                     Bb + (long)nc * bn + (k0 + ch * 8), p);
            } else {
                int kk = e >> 4, ch = e & 15;
                bool p = (n0 + ch * 8) < N;
                int nc = p ? (n0 + ch * 8) : (N - 8);
                cp16(sb + kk * 272 + ch * 16,
                     Bb + (long)(k0 + kk) * bk + nc, p);
            }
        }
    };

    auto compute = [&](int s) {
        const uint32_t sa = smb + (uint32_t)s * STG_BYTES;
        const uint32_t sb = sa + A_BYTES;
#pragma unroll
        for (int ks = 0; ks < 2; ks++) {
            uint32_t afr[2][4];
#pragma unroll
            for (int mf = 0; mf < 2; mf++) {
                if (AKI) ldsm_x4  (sa + a_off[mf] + ks * 32,   afr[mf]);
                else     ldsm_x4_t(sa + a_off[mf] + ks * 4352, afr[mf]);
            }
#pragma unroll
            for (int nf2 = 0; nf2 < 4; nf2++) {
                uint32_t bfr[4];
                if (BKI) ldsm_x4  (sb + b_off + nf2 * 1280 + ks * 32,   bfr);
                else     ldsm_x4_t(sb + b_off + nf2 * 32   + ks * 4352, bfr);
                mma_bf16(acc[0][2 * nf2],     afr[0], bfr);
                mma_bf16(acc[1][2 * nf2],     afr[1], bfr);
                mma_bf16(acc[0][2 * nf2 + 1], afr[0], bfr + 2);
                mma_bf16(acc[1][2 * nf2 + 1], afr[1], bfr + 2);
            }
        }
    };

    // prologue: first pair (group 0)
    issue(0, 0);
    if (KT > 1) issue(1, 1);
    CP_COMMIT();

    int kt = 0;
    for (; kt + 1 < KT; kt += 2) {
        CP_WAIT0();
        __syncthreads();
        if (kt + 2 < KT) {
            issue(kt + 2, (kt + 2) & 3);
            if (kt + 3 < KT) issue(kt + 3, (kt + 3) & 3);
            CP_COMMIT();
        }
        compute(kt & 3);
        compute((kt + 1) & 3);
    }
    if (kt < KT) {                  // odd-KT tail
        CP_WAIT0();
        __syncthreads();
        compute(kt & 3);
    }

    // epilogue
    if (EPI == 3) {
        float* Cb = (float*)Cp + cb * bz;
#pragma unroll
        for (int mf = 0; mf < 2; mf++) {
            int r1 = m0 + warp_m + mf * 16 + gq;
            int r2 = r1 + 8;
            float b1 = bias[r1], b2 = bias[r2];
            float i1 = gamma[r1] * rsqrtf(rvar[r1] + 1e-5f);
            float i2 = gamma[r2] * rsqrtf(rvar[r2] + 1e-5f);
            float s1 = beta[r1] - rmean[r1] * i1;
            float s2 = beta[r2] - rmean[r2] * i2;
#pragma unroll
            for (int nf = 0; nf < 8; nf++) {
                int col = n0 + warp_n + nf * 8 + 2 * qq;
                if (col >= N) continue;
                const float* xr = xres + xb * bz;
                float2 x1 = *(const float2*)(xr + (long)r1 * N + col);
                float2 x2 = *(const float2*)(xr + (long)r2 * N + col);
                float v0 = (acc[mf][nf][0] + b1) * i1 + s1 + x1.x;
                float v1 = (acc[mf][nf][1] + b1) * i1 + s1 + x1.y;
                float v2 = (acc[mf][nf][2] + b2) * i2 + s2 + x2.x;
                float v3 = (acc[mf][nf][3] + b2) * i2 + s2 + x2.y;
                *(float2*)(Cb + (long)r1 * N + col) = make_float2(v0, v1);
                *(float2*)(Cb + (long)r2 * N + col) = make_float2(v2, v3);
            }
        }
    } else {
        const int half = (EPI == 5 && m0 >= 512) ? 1 : 0;
        __nv_bfloat16* Cb = ((__nv_bfloat16*)(half ? Cp2 : Cp)) + cb * bz;
        const int rbase = half ? 512 : 0;
#pragma unroll
        for (int mf = 0; mf < 2; mf++) {
            int r1 = m0 + warp_m + mf * 16 + gq;
            int r2 = r1 + 8;
            float b1 = 0.f, b2 = 0.f;
            if (EPI == 0) { b1 = bias[r1]; b2 = bias[r2]; }
            if (EPI == 5) {
                const float* bp = half ? paux : bias;
                b1 = bp[r1 - rbase]; b2 = bp[r2 - rbase];
            }
            float s1 = 0.f, s2 = 0.f;   // EPI==1 row partial sums
#pragma unroll
            for (int nf = 0; nf < 8; nf++) {
                int col = n0 + warp_n + nf * 8 + 2 * qq;
                if (col >= N) continue;
                float v0 = acc[mf][nf][0], v1 = acc[mf][nf][1];
                float v2 = acc[mf][nf][2], v3 = acc[mf][nf][3];
                if (EPI == 0 || EPI == 5) { v0 += b1; v1 += b1; v2 += b2; v3 += b2; }
                if (EPI == 1) {
                    v0 = __expf(v0 * scale); v1 = __expf(v1 * scale);
                    v2 = __expf(v2 * scale); v3 = __expf(v3 * scale);
                    s1 += v0 + v1; s2 += v2 + v3;
                }
                if (EPI == 4) {
                    float2 iv = *(const float2*)(bias + xb * bz + col);
                    v0 *= iv.x; v1 *= iv.y; v2 *= iv.x; v3 *= iv.y;
                }
                *(uint32_t*)(Cb + (long)(r1 - rbase) * N + col) = bpack(v0, v1);
                *(uint32_t*)(Cb + (long)(r2 - rbase) * N + col) = bpack(v2, v3);
            }
            if (EPI == 1) {
                s1 += __shfl_xor_sync(0xFFFFFFFFu, s1, 1);
                s1 += __shfl_xor_sync(0xFFFFFFFFu, s1, 2);
                s2 += __shfl_xor_sync(0xFFFFFFFFu, s2, 1);
                s2 += __shfl_xor_sync(0xFFFFFFFFu, s2, 2);
                if (qq == 0) {
                    int pidx = blockIdx.x * 2 + (wid >> 2);
                    paux[((long)bz * NTOT + r1) * NPART + pidx] = s1;
                    paux[((long)bz * NTOT + r2) * NPART + pidx] = s2;
                }
            }
        }
    }
}

// ---------------------------------------------------------------------------
// Reduce 26 partials per row -> 1/sum (fixed order, deterministic).
// ---------------------------------------------------------------------------
__global__ void reduce_inv_kernel(const float* __restrict__ part,
                                  float* __restrict__ inv) {
    long r = (long)blockIdx.x * blockDim.x + threadIdx.x;
    if (r >= (long)BH * NTOT) return;
    const float* p = part + r * NPART;
    float s = 0.f;
#pragma unroll
    for (int i = 0; i < NPART; i++) s += p[i];
    inv[r] = 1.f / s;
}

// ---------------------------------------------------------------------------
extern "C" void kernel_launch(void* const* d_in, const int* in_sizes, int n_in,
                              void* d_out, int out_size)
{
    const float* x     = (const float*)d_in[0];
    const float* Wg    = (const float*)d_in[1];
    const float* bg    = (const float*)d_in[2];
    const float* Wth   = (const float*)d_in[3];
    const float* bth   = (const float*)d_in[4];
    const float* Wph   = (const float*)d_in[5];
    const float* bph   = (const float*)d_in[6];
    const float* Ww    = (const float*)d_in[7];
    const float* bw    = (const float*)d_in[8];
    const float* gamma = (const float*)d_in[9];
    const float* beta  = (const float*)d_in[10];
    const float* rmean = (const float*)d_in[11];
    const float* rvar  = (const float*)d_in[12];
    float* out = (float*)d_out;

    __nv_bfloat16 *xb, *xpb, *wb, *gb, *phb, *thb, *yb, *fb;
    float *invb, *partb;
    cudaGetSymbolAddress((void**)&xb,    b_x);
    cudaGetSymbolAddress((void**)&xpb,   b_xp);
    cudaGetSymbolAddress((void**)&wb,    b_w);
    cudaGetSymbolAddress((void**)&gb,    b_g);
    cudaGetSymbolAddress((void**)&phb,   b_ph);
    cudaGetSymbolAddress((void**)&thb,   b_th);
    cudaGetSymbolAddress((void**)&yb,    b_y);
    cudaGetSymbolAddress((void**)&fb,    b_f);
    cudaGetSymbolAddress((void**)&invb,  g_inv);
    cudaGetSymbolAddress((void**)&partb, g_part);

    cudaFuncSetAttribute(tgemm_kernel<5, true,  false>, cudaFuncAttributeMaxDynamicSharedMemorySize, SM_BYTES);
    cudaFuncSetAttribute(tgemm_kernel<0, true,  false>, cudaFuncAttributeMaxDynamicSharedMemorySize, SM_BYTES);
    cudaFuncSetAttribute(tgemm_kernel<1, false, false>, cudaFuncAttributeMaxDynamicSharedMemorySize, SM_BYTES);
    cudaFuncSetAttribute(tgemm_kernel<4, true,  true >, cudaFuncAttributeMaxDynamicSharedMemorySize, SM_BYTES);
    cudaFuncSetAttribute(tgemm_kernel<3, true,  false>, cudaFuncAttributeMaxDynamicSharedMemorySize, SM_BYTES);

    const long WSZ = (long)CI_ * CC;   // 524288

    // 0) all fp32 -> bf16 conversion in one launch (x then Wg|Wph|Wth|Ww)
    {
        long n4 = (long)BB * CC * NTOT / 4;
        long w4 = WSZ / 4;
        long tot = n4 + 4 * w4;
        cvt_all_kernel<<<(unsigned)((tot + 255) / 256), 256>>>(
            (const float4*)x, (__nv_bfloat162*)xb, n4,
            (const float4*)Wg, (const float4*)Wph, (const float4*)Wth, (const float4*)Ww,
            (__nv_bfloat162*)wb, w4);
    }
    // 1) maxpool over bf16 xb (bitwise identical to fp32 pool + round)
    {
        long total = (long)BB * CC * NP;
        maxpool_kernel<<<(unsigned)((total + 255) / 256), 256>>>();
    }

    // 2) fused [g; ph] = [Wg; Wph] @ xp + [bg; bph]  (M=1024, N=1568, K=1024, batch 8)
    {
        dim3 grid((NP + 127) / 128, 1024 / 128, BB);
        tgemm_kernel<5, true, false><<<grid, 256, SM_BYTES>>>(
            wb, CC, 1, 0,
            xpb, NP, 1, (long)CC * NP,
            gb, (long)CI_ * NP,
            1024, NP, CC,
            bg, 0.f, nullptr, nullptr, nullptr, nullptr, nullptr, 0,
            phb, (float*)bph);
    }
    // 3) th = Wth @ x + bth   (M=512, N=6272, K=1024, batch 8)
    {
        dim3 grid(NTOT / 128, CI_ / 128, BB);
        tgemm_kernel<0, true, false><<<grid, 256, SM_BYTES>>>(
            wb + 2 * WSZ, CC, 1, 0,
            xb, NTOT, 1, (long)CC * NTOT,
            thb, (long)CI_ * NTOT,
            CI_, NTOT, CC,
            bth, 0.f, nullptr, nullptr, nullptr, nullptr, nullptr, 0,
            nullptr, nullptr);
    }
    // 4) f = exp(th^T @ ph * d^-0.5) + row partial sums  (M=6272, N=1568, K=256, batch 16)
    {
        dim3 grid((NP + 127) / 128, NTOT / 128, BH);
        tgemm_kernel<1, false, false><<<grid, 256, SM_BYTES>>>(
            thb, 1, NTOT, (long)DD * NTOT,
            phb, NP, 1, (long)DD * NP,
            fb, (long)NTOT * NP,
            NTOT, NP, DD,
            nullptr, 0.0625f, nullptr, nullptr, nullptr, nullptr, nullptr, 0,
            nullptr, partb);
    }
    // 5) reduce partials -> 1/sum
    reduce_inv_kernel<<<(BH * NTOT + 255) / 256, 256>>>(partb, invb);

    // 6) y = (g @ f^T) * colinv   (M=256, N=6272, K=1568, batch 16)
    {
        dim3 grid(NTOT / 128, DD / 128, BH);
        tgemm_kernel<4, true, true><<<grid, 256, SM_BYTES>>>(
            gb, NP, 1, (long)DD * NP,
            fb, 1, NP, (long)NTOT * NP,
            yb, (long)DD * NTOT,
            DD, NTOT, NP,
            invb, 0.f, nullptr, nullptr, nullptr, nullptr, nullptr, NTOT,
            nullptr, nullptr);
    }
    // 7) out = BN(Ww @ y + bw) + x   (M=1024, N=6272, K=512, batch 8)
    {
        dim3 grid(NTOT / 128, CC / 128, BB);
        tgemm_kernel<3, true, false><<<grid, 256, SM_BYTES>>>(
            wb + 3 * WSZ, CI_, 1, 0,
            yb, NTOT, 1, (long)CI_ * NTOT,
            out, (long)CC * NTOT,
            CC, NTOT, CI_,
            bw, 0.f, gamma, beta, rmean, rvar, x, (long)CC * NTOT,
            nullptr, nullptr);
    }
}